// round 1
// baseline (speedup 1.0000x reference)
#include <cuda_runtime.h>

#define T_TOK 20000
#define LDP   152   // padded row stride for [T,150] intermediates (float4-aligned)

// ---- scratch (device globals; no allocation allowed) ----
__device__ __align__(256) float g_AH1[T_TOK * LDP];
__device__ __align__(256) float g_AH2[T_TOK * LDP];
__device__ __align__(256) float g_AP [T_TOK * LDP];
__device__ __align__(256) float g_BP [T_TOK * LDP];
__device__ __align__(256) float g_PP [T_TOK * LDP];
__device__ __align__(256) float g_LG [T_TOK];

// ============================================================
// Generic tiled GEMM: Y[M,150] = opt_relu(X[M,K] @ W[K,150] + bias)
// Y has padded row stride LDP=152. Tile: 64 rows x 160 cols (padded),
// 320 threads, each computes an 8x4 register tile.
// ============================================================
__global__ __launch_bounds__(320) void gemm150(
    const float* __restrict__ X, int ldx, int K,
    const float* __restrict__ W,
    const float* __restrict__ bias,
    float* __restrict__ Y, int M, int dorelu)
{
    __shared__ float Xs[64 * 33];
    __shared__ float Ws[32 * 160];
    const int tid = threadIdx.x;
    const int sg  = tid / 40;      // 0..7  -> 8 consecutive rows
    const int cg  = tid % 40;      // 0..39 -> col group
    const int c0  = cg * 4;
    const int m0  = blockIdx.x * 64;

    float4 acc[8];
#pragma unroll
    for (int r = 0; r < 8; r++) acc[r] = make_float4(0.f, 0.f, 0.f, 0.f);

    const int ktiles = (K + 31) >> 5;
    for (int kt = 0; kt < ktiles; kt++) {
        const int kb = kt << 5;
        for (int idx = tid; idx < 64 * 32; idx += 320) {
            int i = idx >> 5, kk = idx & 31;
            int m = m0 + i, k = kb + kk;
            Xs[i * 33 + kk] = (m < M && k < K) ? X[(long long)m * ldx + k] : 0.f;
        }
        for (int idx = tid; idx < 32 * 160; idx += 320) {
            int kk = idx / 160, c = idx - kk * 160;
            int k = kb + kk;
            Ws[idx] = (k < K && c < 150) ? W[k * 150 + c] : 0.f;
        }
        __syncthreads();
#pragma unroll 4
        for (int kk = 0; kk < 32; kk++) {
            float4 wv = *(const float4*)&Ws[kk * 160 + c0];
#pragma unroll
            for (int r = 0; r < 8; r++) {
                float x = Xs[(sg * 8 + r) * 33 + kk];
                acc[r].x += x * wv.x; acc[r].y += x * wv.y;
                acc[r].z += x * wv.z; acc[r].w += x * wv.w;
            }
        }
        __syncthreads();
    }
    if (c0 >= 150) return;  // pad col-groups write nothing

    float4 bv = make_float4(0.f, 0.f, 0.f, 0.f);
    if (bias) {
        bv.x = bias[c0];
        bv.y = (c0 + 1 < 150) ? bias[c0 + 1] : 0.f;
        bv.z = (c0 + 2 < 150) ? bias[c0 + 2] : 0.f;
        bv.w = (c0 + 3 < 150) ? bias[c0 + 3] : 0.f;
    }
#pragma unroll
    for (int r = 0; r < 8; r++) {
        int m = m0 + sg * 8 + r;
        if (m < M) {
            float4 v = acc[r];
            v.x += bv.x; v.y += bv.y; v.z += bv.z; v.w += bv.w;
            if (dorelu) {
                v.x = fmaxf(v.x, 0.f); v.y = fmaxf(v.y, 0.f);
                v.z = fmaxf(v.z, 0.f); v.w = fmaxf(v.w, 0.f);
            }
            *(float4*)&Y[(long long)m * LDP + c0] = v;  // writes into 152-padded row
        }
    }
}

// ============================================================
// logits[r] = AH2[r,:150] . W3 + b3   (warp per row)
// ============================================================
__global__ void logits_k(const float* __restrict__ AH2,
                         const float* __restrict__ W3,
                         const float* __restrict__ b3,
                         float* __restrict__ logits, int M)
{
    int warp = (blockIdx.x * blockDim.x + threadIdx.x) >> 5;
    int lane = threadIdx.x & 31;
    if (warp >= M) return;
    float sum = 0.f;
    for (int c = lane; c < 150; c += 32)
        sum += AH2[(long long)warp * LDP + c] * W3[c];
#pragma unroll
    for (int o = 16; o; o >>= 1) sum += __shfl_xor_sync(0xffffffffu, sum, o);
    if (lane == 0) logits[warp] = sum + b3[0];
}

// ============================================================
// Span kernel: blockIdx.y -> width n-1, blockIdx.x -> tile of 64 starts.
// Stage A: softmax weights + H1 = relu(AP[s]+BP[e]+sum_j w_j PP[s+j]+b1)
// Stage B: H2 = relu(H1 @ W2 + b2); score = H2.W3 + b3
// Dynamic smem layout (floats):
//   W2s   [50*160] @ 0
//   H1s   [64*160] @ 8000
//   wgt   [64*10]  @ 18240
//   red   [64*41]  @ 18880
//   b1s   [160]    @ 21504
//   b2s   [160]    @ 21664
//   W3s   [160]    @ 21824      total 21984 floats = 87936 B
// ============================================================
#define SPAN_SMEM_FLOATS 21984

__global__ __launch_bounds__(320) void span_k(
    const float* __restrict__ AP, const float* __restrict__ BP,
    const float* __restrict__ PP, const float* __restrict__ logits,
    const float* __restrict__ W2, const float* __restrict__ b1,
    const float* __restrict__ b2, const float* __restrict__ W3,
    const float* __restrict__ b3, float* __restrict__ out)
{
    extern __shared__ float sm[];
    float* W2s = sm;
    float* H1s = sm + 8000;
    float* wgt = sm + 18240;
    float* red = sm + 18880;
    float* b1s = sm + 21504;
    float* b2s = sm + 21664;
    float* W3s = sm + 21824;

    const int n  = blockIdx.y + 1;
    const int S  = T_TOK - n + 1;
    const int s0 = blockIdx.x * 64;
    if (s0 >= S) return;  // uniform per block

    const int tid = threadIdx.x;
    const int sg  = tid / 40;
    const int cg  = tid % 40;
    const int c0  = cg * 4;

    // constants into smem (padded with zeros beyond col 149)
    for (int c = tid; c < 160; c += 320) {
        b1s[c] = (c < 150) ? b1[c] : 0.f;
        b2s[c] = (c < 150) ? b2[c] : 0.f;
        W3s[c] = (c < 150) ? W3[c] : 0.f;
    }

    // per-span softmax weights over the n window logits
    if (tid < 64) {
        int s = s0 + tid;
        if (s < S) {
            float mx = -1e30f;
            for (int j = 0; j < n; j++) mx = fmaxf(mx, logits[s + j]);
            float sum = 0.f;
            for (int j = 0; j < n; j++) {
                float e = __expf(logits[s + j] - mx);
                wgt[tid * 10 + j] = e;
                sum += e;
            }
            float inv = 1.f / sum;
            for (int j = 0; j < n; j++) wgt[tid * 10 + j] *= inv;
            for (int j = n; j < 10; j++) wgt[tid * 10 + j] = 0.f;
        } else {
            for (int j = 0; j < 10; j++) wgt[tid * 10 + j] = 0.f;
        }
    }
    __syncthreads();

    // ---- Stage A: build H1 tile [64 x 150] in smem ----
    if (c0 < 150) {
#pragma unroll
        for (int r = 0; r < 8; r++) {
            int i = sg * 8 + r;
            int s = s0 + i;
            float4 v;
            if (s < S) {
                int e = s + n - 1;
                float4 a4 = *(const float4*)&AP[(long long)s * LDP + c0];
                float4 q4 = *(const float4*)&BP[(long long)e * LDP + c0];
                float4 o4 = *(const float4*)&b1s[c0];
                v.x = a4.x + q4.x + o4.x;
                v.y = a4.y + q4.y + o4.y;
                v.z = a4.z + q4.z + o4.z;
                v.w = a4.w + q4.w + o4.w;
                for (int j = 0; j < n; j++) {
                    float w = wgt[i * 10 + j];
                    float4 p4 = *(const float4*)&PP[(long long)(s + j) * LDP + c0];
                    v.x += w * p4.x; v.y += w * p4.y;
                    v.z += w * p4.z; v.w += w * p4.w;
                }
                v.x = fmaxf(v.x, 0.f); v.y = fmaxf(v.y, 0.f);
                v.z = fmaxf(v.z, 0.f); v.w = fmaxf(v.w, 0.f);
            } else {
                v = make_float4(0.f, 0.f, 0.f, 0.f);
            }
            *(float4*)&H1s[i * 160 + c0] = v;
        }
    }
    __syncthreads();

    // ---- Stage B: H2 = relu(H1 @ W2 + b2), 3 k-tiles of 50 ----
    float a0[8], a1[8], a2[8], a3[8];
#pragma unroll
    for (int r = 0; r < 8; r++) {
        a0[r] = b2s[c0];     a1[r] = b2s[c0 + 1];
        a2[r] = b2s[c0 + 2]; a3[r] = b2s[c0 + 3];
    }
    for (int kt = 0; kt < 3; kt++) {
        const int kb = kt * 50;
        for (int idx = tid; idx < 50 * 160; idx += 320) {
            int kk = idx / 160, c = idx - kk * 160;
            W2s[idx] = (c < 150) ? W2[(kb + kk) * 150 + c] : 0.f;
        }
        __syncthreads();
#pragma unroll 2
        for (int kk = 0; kk < 50; kk++) {
            float4 wv = *(const float4*)&W2s[kk * 160 + c0];
#pragma unroll
            for (int r = 0; r < 8; r++) {
                float h = H1s[(sg * 8 + r) * 160 + kb + kk];
                a0[r] += h * wv.x; a1[r] += h * wv.y;
                a2[r] += h * wv.z; a3[r] += h * wv.w;
            }
        }
        __syncthreads();
    }

    // ---- W3 dot (pad cols of W3s are zero) + block reduction ----
#pragma unroll
    for (int r = 0; r < 8; r++) {
        float p = fmaxf(a0[r], 0.f) * W3s[c0]
                + fmaxf(a1[r], 0.f) * W3s[c0 + 1]
                + fmaxf(a2[r], 0.f) * W3s[c0 + 2]
                + fmaxf(a3[r], 0.f) * W3s[c0 + 3];
        red[(sg * 8 + r) * 41 + cg] = p;
    }
    __syncthreads();

    if (tid < 64) {
        int s = s0 + tid;
        if (s < S) {
            float sum = 0.f;
            for (int j = 0; j < 40; j++) sum += red[tid * 41 + j];
            long long off = (long long)(n - 1) * (T_TOK + 1)
                          - (long long)(n - 1) * n / 2;
            out[off + s] = sum + b3[0];
        }
    }
}

// ============================================================
extern "C" void kernel_launch(void* const* d_in, const int* in_sizes, int n_in,
                              void* d_out, int out_size)
{
    const float* embeds  = (const float*)d_in[0];
    const float* states  = (const float*)d_in[1];
    const float* attn_W1 = (const float*)d_in[2];
    const float* attn_b1 = (const float*)d_in[3];
    const float* attn_W2 = (const float*)d_in[4];
    const float* attn_b2 = (const float*)d_in[5];
    const float* attn_W3 = (const float*)d_in[6];
    const float* attn_b3 = (const float*)d_in[7];
    const float* sc_W1   = (const float*)d_in[8];
    const float* sc_b1   = (const float*)d_in[9];
    const float* sc_W2   = (const float*)d_in[10];
    const float* sc_b2   = (const float*)d_in[11];
    const float* sc_W3   = (const float*)d_in[12];
    const float* sc_b3   = (const float*)d_in[13];
    float* out = (float*)d_out;

    float *AH1, *AH2, *AP, *BP, *PP, *LG;
    cudaGetSymbolAddress((void**)&AH1, g_AH1);
    cudaGetSymbolAddress((void**)&AH2, g_AH2);
    cudaGetSymbolAddress((void**)&AP,  g_AP);
    cudaGetSymbolAddress((void**)&BP,  g_BP);
    cudaGetSymbolAddress((void**)&PP,  g_PP);
    cudaGetSymbolAddress((void**)&LG,  g_LG);

    const int gm = (T_TOK + 63) / 64;  // 313

    // attention MLP
    gemm150<<<gm, 320>>>(states, 400, 400, attn_W1, attn_b1, AH1, T_TOK, 1);
    gemm150<<<gm, 320>>>(AH1,   LDP, 150, attn_W2, attn_b2, AH2, T_TOK, 1);
    logits_k<<<(T_TOK * 32 + 255) / 256, 256>>>(AH2, attn_W3, attn_b3, LG, T_TOK);

    // span layer-1 projections (bias deferred to span kernel)
    gemm150<<<gm, 320>>>(states, 400, 400, sc_W1,             nullptr, AP, T_TOK, 0);
    gemm150<<<gm, 320>>>(states, 400, 400, sc_W1 + 400 * 150, nullptr, BP, T_TOK, 0);
    gemm150<<<gm, 320>>>(embeds, 300, 300, sc_W1 + 800 * 150, nullptr, PP, T_TOK, 0);

    // fused span scorer
    size_t smem = SPAN_SMEM_FLOATS * sizeof(float);  // 87936 B
    cudaFuncSetAttribute(span_k, cudaFuncAttributeMaxDynamicSharedMemorySize, (int)smem);
    span_k<<<dim3(gm, 10), 320, smem>>>(AP, BP, PP, LG,
                                        sc_W2, sc_b1, sc_b2, sc_W3, sc_b3, out);
}